// round 1
// baseline (speedup 1.0000x reference)
#include <cuda_runtime.h>
#include <cuda_bf16.h>
#include <math_constants.h>

// Problem dims
#define BATCH 8
#define SEQ   2048
#define WIDTH 768
#define HEAD  64
#define MROWS (BATCH * SEQ)   // 16384

// Scratch for Q, K, V (scale folded into Q)
__device__ float g_Q[MROWS * HEAD];
__device__ float g_K[MROWS * HEAD];
__device__ float g_V[MROWS * HEAD];

// ---------------------------------------------------------------------------
// Kernel 1: fused QKV projection.
// C[M=16384, 192] = x[M, 768] @ [Wq|Wk|Wv][768, 192] + bias
// Block: 64 rows x 192 cols. 256 threads, each 4x12 register tile.
// Thread (ty,tx): rows ty*4..+4, cols tx*12..+12 (contiguous -> float4 W loads)
// ---------------------------------------------------------------------------
__global__ __launch_bounds__(256) void qkv_kernel(
    const float* __restrict__ x,
    const float* __restrict__ Wq, const float* __restrict__ bq,
    const float* __restrict__ Wk, const float* __restrict__ bk,
    const float* __restrict__ Wv, const float* __restrict__ bv)
{
    __shared__ float xs[64 * 33];    // 64 rows x 32 k, pad 33
    __shared__ float ws[32 * 192];   // 32 k x 192 cols

    const int tid = threadIdx.x;
    const int ty = tid >> 4;         // 0..15
    const int tx = tid & 15;         // 0..15
    const int block_row = blockIdx.x * 64;

    float acc[4][12];
#pragma unroll
    for (int i = 0; i < 4; ++i)
#pragma unroll
        for (int j = 0; j < 12; ++j) acc[i][j] = 0.0f;

    for (int kk = 0; kk < WIDTH; kk += 32) {
        // load x tile: 64x32 = 2048 elems
#pragma unroll
        for (int t = 0; t < 8; ++t) {
            int i = t * 256 + tid;
            int r = i >> 5, c = i & 31;
            xs[r * 33 + c] = x[(size_t)(block_row + r) * WIDTH + kk + c];
        }
        // load W tile: 32 x 192 (Wq | Wk | Wv)
#pragma unroll
        for (int t = 0; t < 8; ++t) {
            int i = t * 256 + tid;
            int k = i >> 6, h = i & 63;
            int gk = (kk + k) * HEAD + h;
            ws[k * 192 + h]       = Wq[gk];
            ws[k * 192 + 64 + h]  = Wk[gk];
            ws[k * 192 + 128 + h] = Wv[gk];
        }
        __syncthreads();

#pragma unroll
        for (int k = 0; k < 32; ++k) {
            float4 w0 = *(const float4*)&ws[k * 192 + tx * 12];
            float4 w1 = *(const float4*)&ws[k * 192 + tx * 12 + 4];
            float4 w2 = *(const float4*)&ws[k * 192 + tx * 12 + 8];
            float xr[4];
#pragma unroll
            for (int i = 0; i < 4; ++i) xr[i] = xs[(ty * 4 + i) * 33 + k];
#pragma unroll
            for (int i = 0; i < 4; ++i) {
                float xv = xr[i];
                acc[i][0]  += xv * w0.x;  acc[i][1]  += xv * w0.y;
                acc[i][2]  += xv * w0.z;  acc[i][3]  += xv * w0.w;
                acc[i][4]  += xv * w1.x;  acc[i][5]  += xv * w1.y;
                acc[i][6]  += xv * w1.z;  acc[i][7]  += xv * w1.w;
                acc[i][8]  += xv * w2.x;  acc[i][9]  += xv * w2.y;
                acc[i][10] += xv * w2.z;  acc[i][11] += xv * w2.w;
            }
        }
        __syncthreads();
    }

    const float scale = 0.125f;  // 1/sqrt(64), folded into Q
#pragma unroll
    for (int i = 0; i < 4; ++i) {
        int row = block_row + ty * 4 + i;
#pragma unroll
        for (int j = 0; j < 12; ++j) {
            int col = tx * 12 + j;
            float v = acc[i][j];
            if (col < 64) {
                g_Q[(size_t)row * HEAD + col] = (v + bq[col]) * scale;
            } else if (col < 128) {
                g_K[(size_t)row * HEAD + (col - 64)] = v + bk[col - 64];
            } else {
                g_V[(size_t)row * HEAD + (col - 128)] = v + bv[col - 128];
            }
        }
    }
}

// ---------------------------------------------------------------------------
// Kernel 2: flash-style attention, Br = Bc = 64.
// grid (SEQ/64, BATCH), 256 threads.
// Thread (ty,tx): score tile rows ty*4..+4, cols tx*4..+4; same for O (cols = h).
// Row-group of 16 tx-lanes reduces max/sum via shfl.
// Mask bit-packed via ballot: 64x64 bits = 128 words.
// smem (dynamic, 67584 B):
//   qs  [64][65]   Q tile
//   kst [64(h)][68] K tile transposed (h-major) -> float4 loads over key cols
//   vs  [64][64]   V tile
//   ps  [64][65]   P tile (softmaxed scores)
//   msb [128]      mask bits
// ---------------------------------------------------------------------------
#define ATTN_SMEM_BYTES 67584

__global__ __launch_bounds__(256) void attn_kernel(
    const int* __restrict__ mask, float* __restrict__ out)
{
    extern __shared__ float sm[];
    float* qs  = sm;                   // 64*65 = 4160
    float* kst = sm + 4160;            // 64*68 = 4352
    float* vs  = sm + 4160 + 4352;     // 64*64 = 4096
    float* ps  = sm + 4160 + 4352 + 4096;          // 64*65 = 4160
    unsigned* msb = (unsigned*)(sm + 4160 + 4352 + 4096 + 4160); // 128 words

    const int tid = threadIdx.x;
    const int ty = tid >> 4;
    const int tx = tid & 15;
    const int b  = blockIdx.y;
    const int q0 = blockIdx.x * 64;

    // load Q tile
#pragma unroll
    for (int t = 0; t < 16; ++t) {
        int i = t * 256 + tid;
        int r = i >> 6, h = i & 63;
        qs[r * 65 + h] = g_Q[((size_t)(b * SEQ + q0 + r)) * HEAD + h];
    }

    float acc[4][4];
    float m[4], l[4];
#pragma unroll
    for (int i = 0; i < 4; ++i) {
        m[i] = -1e30f; l[i] = 0.0f;
#pragma unroll
        for (int j = 0; j < 4; ++j) acc[i][j] = 0.0f;
    }

    for (int k0 = 0; k0 < SEQ; k0 += 64) {
        __syncthreads();  // prior iteration done reading ps/vs

        // load K (transposed in smem), V
#pragma unroll
        for (int t = 0; t < 16; ++t) {
            int i = t * 256 + tid;
            int r = i >> 6, h = i & 63;
            size_t g = ((size_t)(b * SEQ + k0 + r)) * HEAD + h;
            kst[h * 68 + r] = g_K[g];
            vs[r * 64 + h]  = g_V[g];
        }
        // load + bitpack mask chunk
#pragma unroll
        for (int t = 0; t < 16; ++t) {
            int i = t * 256 + tid;
            int r = i >> 6, c = i & 63;
            int mv = mask[(size_t)(q0 + r) * SEQ + k0 + c];
            unsigned bal = __ballot_sync(0xffffffffu, mv != 0);
            if ((tid & 31) == 0) msb[r * 2 + (c >> 5)] = bal;
        }
        __syncthreads();

        // S = Q @ K^T  (scale already folded into Q)
        float s[4][4];
#pragma unroll
        for (int i = 0; i < 4; ++i)
#pragma unroll
            for (int j = 0; j < 4; ++j) s[i][j] = 0.0f;

#pragma unroll 16
        for (int h = 0; h < 64; ++h) {
            float4 kv = *(const float4*)&kst[h * 68 + tx * 4];
#pragma unroll
            for (int i = 0; i < 4; ++i) {
                float qv = qs[(ty * 4 + i) * 65 + h];
                s[i][0] += qv * kv.x;
                s[i][1] += qv * kv.y;
                s[i][2] += qv * kv.z;
                s[i][3] += qv * kv.w;
            }
        }

        // mask + online softmax
#pragma unroll
        for (int i = 0; i < 4; ++i) {
            int row = ty * 4 + i;
            unsigned w = msb[row * 2 + (tx >> 3)];
            float rmax = -1e30f;
#pragma unroll
            for (int j = 0; j < 4; ++j) {
                int c = tx * 4 + j;
                bool keep = (w >> (c & 31)) & 1u;
                s[i][j] = keep ? s[i][j] : -1e30f;
                rmax = fmaxf(rmax, s[i][j]);
            }
#pragma unroll
            for (int o = 8; o >= 1; o >>= 1)
                rmax = fmaxf(rmax, __shfl_xor_sync(0xffffffffu, rmax, o));

            float mnew = fmaxf(m[i], rmax);
            float corr = __expf(m[i] - mnew);
            float rsum = 0.0f;
#pragma unroll
            for (int j = 0; j < 4; ++j) {
                float p = __expf(s[i][j] - mnew);
                ps[row * 65 + tx * 4 + j] = p;
                rsum += p;
            }
#pragma unroll
            for (int o = 8; o >= 1; o >>= 1)
                rsum += __shfl_xor_sync(0xffffffffu, rsum, o);

            l[i] = l[i] * corr + rsum;
            m[i] = mnew;
#pragma unroll
            for (int j = 0; j < 4; ++j) acc[i][j] *= corr;
        }
        __syncthreads();  // ps complete

        // O += P @ V
#pragma unroll 16
        for (int kc = 0; kc < 64; ++kc) {
            float4 vv = *(const float4*)&vs[kc * 64 + tx * 4];
#pragma unroll
            for (int i = 0; i < 4; ++i) {
                float p = ps[(ty * 4 + i) * 65 + kc];
                acc[i][0] += p * vv.x;
                acc[i][1] += p * vv.y;
                acc[i][2] += p * vv.z;
                acc[i][3] += p * vv.w;
            }
        }
    }

    // write O = acc / l
#pragma unroll
    for (int i = 0; i < 4; ++i) {
        float inv = 1.0f / l[i];
        float4 o4;
        o4.x = acc[i][0] * inv;
        o4.y = acc[i][1] * inv;
        o4.z = acc[i][2] * inv;
        o4.w = acc[i][3] * inv;
        size_t row = (size_t)(b * SEQ + q0 + ty * 4 + i);
        *(float4*)&out[row * HEAD + tx * 4] = o4;
    }
}

// ---------------------------------------------------------------------------
extern "C" void kernel_launch(void* const* d_in, const int* in_sizes, int n_in,
                              void* d_out, int out_size)
{
    const float* x  = (const float*)d_in[0];
    const float* Wq = (const float*)d_in[1];
    const float* bq = (const float*)d_in[2];
    const float* Wk = (const float*)d_in[3];
    const float* bk = (const float*)d_in[4];
    const float* Wv = (const float*)d_in[5];
    const float* bv = (const float*)d_in[6];
    const int* mask = (const int*)d_in[7];
    float* out = (float*)d_out;

    cudaFuncSetAttribute(attn_kernel,
                         cudaFuncAttributeMaxDynamicSharedMemorySize,
                         ATTN_SMEM_BYTES);

    qkv_kernel<<<MROWS / 64, 256>>>(x, Wq, bq, Wk, bk, Wv, bv);
    attn_kernel<<<dim3(SEQ / 64, BATCH), 256, ATTN_SMEM_BYTES>>>(mask, out);
}